// round 5
// baseline (speedup 1.0000x reference)
#include <cuda_runtime.h>
#include <cuda_fp16.h>
#include <cstdint>
#include <math.h>

// ---------------- problem constants ----------------
#define NS   5760
#define CO   640
#define KD   192
#define NPOS 16
#define B_   8
#define WAY_ 5
#define NQ_  75
#define P_   9
#define NTOT (NS * NPOS)     // 92160
#define KE2  576             // 3 * 192 fp16-split K
#define TNB  64              // N per block = 4 images
#define KC   48              // K halves per chunk
#define NCH  12              // 576 / 48

// ---------------- device scratch ----------------
__device__ __align__(128) __half g_X[(size_t)NTOT * KE2];  // 106 MB
__device__ __align__(128) __half g_W[(size_t)CO * KE2];    // 737 KB
__device__ float g_u[(size_t)NS * CO];

__device__ __forceinline__ uint32_t smem_u32(const void* p) {
    uint32_t a;
    asm("{ .reg .u64 t; cvta.to.shared.u64 t, %1; cvt.u32.u64 %0, t; }"
        : "=r"(a) : "l"(p));
    return a;
}

// ---------------------------------------------------------------------------
// Prep W: fp16 split, K-concat [w0 | w0 | w1]
// ---------------------------------------------------------------------------
__global__ void k_prepw(const float* __restrict__ w) {
    int i = blockIdx.x * 256 + threadIdx.x;
    if (i >= CO * KD) return;
    int ch = i / KD, k = i % KD;
    float v = w[i];
    __half h0 = __float2half_rn(v);
    __half h1 = __float2half_rn(v - __half2float(h0));
    size_t b = (size_t)ch * KE2;
    g_W[b + k]       = h0;
    g_W[b + 192 + k] = h0;
    g_W[b + 384 + k] = h1;
}

// ---------------------------------------------------------------------------
// Prep X: im2col + fp16 split, K-concat [x0 | x1 | x0]. One block per image.
// ---------------------------------------------------------------------------
__global__ void __launch_bounds__(128) k_prepx(const float* __restrict__ data) {
    __shared__ __align__(16) __half xsm[NPOS * KE2];   // 18 KB
    const int s = blockIdx.x, t = threadIdx.x;
    const float* img = data + (size_t)s * 3072;
    for (int i = t; i < 3072; i += 128) {
        float v = img[i];
        int ci = i >> 10, row = (i >> 5) & 31, col = i & 31;
        int k   = ci * 64 + (row & 7) * 8 + (col & 7);
        int pos = (row >> 3) * 4 + (col >> 3);
        __half h0 = __float2half_rn(v);
        __half h1 = __float2half_rn(v - __half2float(h0));
        int r = pos * KE2;
        xsm[r + k]       = h0;
        xsm[r + 192 + k] = h1;
        xsm[r + 384 + k] = h0;
    }
    __syncthreads();
    uint4* dst = reinterpret_cast<uint4*>(g_X + (size_t)s * NPOS * KE2);
    const uint4* src = reinterpret_cast<const uint4*>(xsm);
    for (int g = t; g < NPOS * KE2 / 8; g += 128) dst[g] = src[g];
}

// ---------------------------------------------------------------------------
// Fused GEMM + norms, ldmatrix edition. F[640,64] per block, then
// per-position L2-norm + pool + final L2-norm -> g_u (4 images/block).
// ---------------------------------------------------------------------------
#define BST     584                       // B row stride (halves): 1168 B
#define AST     56                        // A row stride (halves): 112 B
#define OFF_B   0
#define BSZ     (64 * BST * 2)            // 74752
#define OFF_A   BSZ
#define ABUF_SZ (640 * AST * 2)           // 71680
#define OFF_SSQ (OFF_A + 2 * ABUF_SZ)     // 218112
#define OFF_SS2 (OFF_SSQ + 256)
#define OFF_VSM (OFF_SS2 + 16)
#define SMT     (OFF_VSM + 10240)         // 228624

#define LDSM4(r0, r1, r2, r3, ad) \
    asm volatile("ldmatrix.sync.aligned.m8n8.x4.shared.b16 {%0,%1,%2,%3},[%4];" \
                 : "=r"(r0), "=r"(r1), "=r"(r2), "=r"(r3) : "r"(ad))

__global__ void __launch_bounds__(640, 1) k_gemm() {
    extern __shared__ char sm[];
    const int t = threadIdx.x, w = t >> 5, lane = t & 31;
    const int bid = blockIdx.x;
    const uint32_t sb = smem_u32(sm);
    float* ssq = reinterpret_cast<float*>(sm + OFF_SSQ);
    float* ss2 = reinterpret_cast<float*>(sm + OFF_SS2);
    float* vsm = reinterpret_cast<float*>(sm + OFF_VSM);

    if (t < 64) ssq[t] = 0.f;
    if (t < 4)  ss2[t] = 0.f;

    // --- A chunk via cp.async: 3840 x 16B, 6 per thread, 96B/row coalesced ---
    auto issueA = [&](int c, int buf) {
        const int kc = KC * c;
#pragma unroll
        for (int i = 0; i < 6; i++) {
            int g = t + 640 * i;
            int row = g / 6, part = g % 6;
            const __half* src = g_W + (size_t)row * KE2 + kc + part * 8;
            uint32_t dst = sb + OFF_A + buf * ABUF_SZ + row * (AST * 2) + part * 16;
            asm volatile("cp.async.cg.shared.global [%0], [%1], 16;"
                         :: "r"(dst), "l"(src));
        }
    };
    issueA(0, 0);
    asm volatile("cp.async.commit_group;");

    // --- stage B (64 rows x 576 halves) ---
    const __half* Xb = g_X + (size_t)bid * TNB * KE2;
    for (int g = t; g < 64 * 72; g += 640) {
        int row = g / 72, part = g % 72;
        uint4 v = *reinterpret_cast<const uint4*>(Xb + (size_t)row * KE2 + part * 8);
        *reinterpret_cast<uint4*>(sm + OFF_B + row * (BST * 2) + part * 16) = v;
    }

    float acc[2][8][4];
#pragma unroll
    for (int mt = 0; mt < 2; mt++)
#pragma unroll
        for (int nt = 0; nt < 8; nt++)
#pragma unroll
            for (int c = 0; c < 4; c++) acc[mt][nt][c] = 0.f;

    // ldmatrix per-lane base addresses
    const int lm = lane >> 3;
    const uint32_t aAddr = sb + OFF_A +
        ((w * 32 + (lm & 1) * 8 + (lane & 7)) * AST + (lm >> 1) * 8) * 2;
    const uint32_t bAddr = sb + OFF_B +
        (((lm >> 1) * 8 + (lane & 7)) * BST + (lm & 1) * 8) * 2;

    for (int c = 0; c < NCH; c++) {
        const int buf = c & 1;
        if (c + 1 < NCH) {
            issueA(c + 1, buf ^ 1);
            asm volatile("cp.async.commit_group;");
            asm volatile("cp.async.wait_group 1;");
        } else {
            asm volatile("cp.async.wait_group 0;");
        }
        __syncthreads();

#pragma unroll
        for (int ks = 0; ks < 3; ks++) {
            uint32_t a0[4], a1[4];
            uint32_t aBase = aAddr + buf * ABUF_SZ + ks * 32;
            LDSM4(a0[0], a0[1], a0[2], a0[3], aBase);
            LDSM4(a1[0], a1[1], a1[2], a1[3], aBase + 16 * AST * 2);
#pragma unroll
            for (int ntp = 0; ntp < 4; ntp++) {
                uint32_t b[4];
                LDSM4(b[0], b[1], b[2], b[3],
                      bAddr + ntp * (16 * BST * 2) + c * (KC * 2) + ks * 32);
#pragma unroll
                for (int sub = 0; sub < 2; sub++) {
                    int nt = 2 * ntp + sub;
                    asm volatile(
                        "mma.sync.aligned.m16n8k16.row.col.f32.f16.f16.f32 "
                        "{%0,%1,%2,%3},{%4,%5,%6,%7},{%8,%9},{%0,%1,%2,%3};"
                        : "+f"(acc[0][nt][0]), "+f"(acc[0][nt][1]),
                          "+f"(acc[0][nt][2]), "+f"(acc[0][nt][3])
                        : "r"(a0[0]), "r"(a0[1]), "r"(a0[2]), "r"(a0[3]),
                          "r"(b[2 * sub]), "r"(b[2 * sub + 1]));
                    asm volatile(
                        "mma.sync.aligned.m16n8k16.row.col.f32.f16.f16.f32 "
                        "{%0,%1,%2,%3},{%4,%5,%6,%7},{%8,%9},{%0,%1,%2,%3};"
                        : "+f"(acc[1][nt][0]), "+f"(acc[1][nt][1]),
                          "+f"(acc[1][nt][2]), "+f"(acc[1][nt][3])
                        : "r"(a1[0]), "r"(a1[1]), "r"(a1[2]), "r"(a1[3]),
                          "r"(b[2 * sub]), "r"(b[2 * sub + 1]));
                }
            }
        }
        __syncthreads();
    }

    // ---- epilogue: per-position channel L2-norm ----
    {
        float cs[16];
#pragma unroll
        for (int nt = 0; nt < 8; nt++)
#pragma unroll
            for (int par = 0; par < 2; par++) {
                float s = 0.f;
#pragma unroll
                for (int mt = 0; mt < 2; mt++) {
                    float x0 = acc[mt][nt][par], x1 = acc[mt][nt][2 + par];
                    s = fmaf(x0, x0, s);
                    s = fmaf(x1, x1, s);
                }
                cs[nt * 2 + par] = s;
            }
#pragma unroll
        for (int i = 0; i < 16; i++) {
            cs[i] += __shfl_xor_sync(0xffffffffu, cs[i], 4);
            cs[i] += __shfl_xor_sync(0xffffffffu, cs[i], 8);
            cs[i] += __shfl_xor_sync(0xffffffffu, cs[i], 16);
        }
        if (lane < 4) {
#pragma unroll
            for (int nt = 0; nt < 8; nt++)
#pragma unroll
                for (int par = 0; par < 2; par++)
                    atomicAdd(&ssq[nt * 8 + lane * 2 + par], cs[nt * 2 + par]);
        }
    }
    __syncthreads();
    if (t < 64) ssq[t] = 1.f / fmaxf(sqrtf(ssq[t]), 1e-12f);
    __syncthreads();

    // ---- pool over positions + final channel L2-norm ----
    float sq[4] = {0.f, 0.f, 0.f, 0.f};
#pragma unroll
    for (int mt = 0; mt < 2; mt++)
#pragma unroll
        for (int h = 0; h < 2; h++)
#pragma unroll
            for (int j = 0; j < 4; j++) {
                float s = 0.f;
#pragma unroll
                for (int ntl = 0; ntl < 2; ntl++) {
                    int nt = 2 * j + ntl;
#pragma unroll
                    for (int par = 0; par < 2; par++) {
                        int col = nt * 8 + (lane & 3) * 2 + par;
                        s = fmaf(acc[mt][nt][h * 2 + par], ssq[col], s);
                    }
                }
                s += __shfl_xor_sync(0xffffffffu, s, 1);
                s += __shfl_xor_sync(0xffffffffu, s, 2);
                if ((lane & 3) == 0) {
                    int row = w * 32 + mt * 16 + h * 8 + (lane >> 2);
                    float v = s * 0.0625f;
                    vsm[row * 4 + j] = v;
                    sq[j] = fmaf(v, v, sq[j]);
                }
            }
#pragma unroll
    for (int j = 0; j < 4; j++) {
        sq[j] += __shfl_xor_sync(0xffffffffu, sq[j], 4);
        sq[j] += __shfl_xor_sync(0xffffffffu, sq[j], 8);
        sq[j] += __shfl_xor_sync(0xffffffffu, sq[j], 16);
    }
    if (lane == 0)
#pragma unroll
        for (int j = 0; j < 4; j++) atomicAdd(&ss2[j], sq[j]);
    __syncthreads();
    if (t < 4) ss2[t] = 1.f / fmaxf(sqrtf(ss2[t]), 1e-12f);
    __syncthreads();

    for (int g = t; g < 2560; g += 640) {
        int ch = g >> 2, j = g & 3;
        g_u[(size_t)(4 * bid + j) * CO + ch] = vsm[ch * 4 + j] * ss2[j];
    }
}

// ---------------------------------------------------------------------------
// Sim + greedy pruning (unchanged passing version).
// ---------------------------------------------------------------------------
#define QSTRIDE 644

__global__ void __launch_bounds__(128) k_sim(float* __restrict__ out) {
    __shared__ float qsm[9 * QSTRIDE];
    __shared__ float ssm[9 * QSTRIDE];
    __shared__ float simm[81];

    const int b = blockIdx.x / NQ_;
    const int n = blockIdx.x % NQ_;
    const int t = threadIdx.x;

    const float* qb = g_u + ((size_t)(b * 80 + WAY_ + n) * P_) * CO;
    for (int i = t; i < 9 * 160; i += 128) {
        int r = i / 160, c4 = (i % 160) * 4;
        *reinterpret_cast<float4*>(&qsm[r * QSTRIDE + c4]) =
            *reinterpret_cast<const float4*>(qb + (size_t)r * CO + c4);
    }

    for (int m = 0; m < WAY_; m++) {
        const float* sb2 = g_u + ((size_t)(b * 80 + m) * P_) * CO;
        __syncthreads();
        for (int i = t; i < 9 * 160; i += 128) {
            int r = i / 160, c4 = (i % 160) * 4;
            *reinterpret_cast<float4*>(&ssm[r * QSTRIDE + c4]) =
                *reinterpret_cast<const float4*>(sb2 + (size_t)r * CO + c4);
        }
        __syncthreads();

        if (t < 81) {
            const int h = t / 9, wq = t % 9;
            const float* sr = &ssm[h * QSTRIDE];
            const float* qr = &qsm[wq * QSTRIDE];
            float d = 0.f;
            for (int c = 0; c < CO; c += 4) {
                float4 a = *reinterpret_cast<const float4*>(sr + c);
                float4 q = *reinterpret_cast<const float4*>(qr + c);
                d = fmaf(a.x, q.x, d);
                d = fmaf(a.y, q.y, d);
                d = fmaf(a.z, q.z, d);
                d = fmaf(a.w, q.w, d);
            }
            simm[t] = d;
        }
        __syncthreads();

        if (t < 32) {
            float v0 = simm[t];
            float v1 = simm[t + 32];
            float v2 = (t + 64 < 81) ? simm[t + 64] : -1e30f;
            unsigned rmask = 0x1FFu, cmask = 0x1FFu;
            float totalv = 0.f, beta = 1.f;
            for (int it = 0; it < 9; it++) {
                float bv = -1e30f;
                int bidx = 999;
                int j = t;
                if (((rmask >> (j / 9)) & 1) && ((cmask >> (j % 9)) & 1)) {
                    bv = v0; bidx = j;
                }
                j = t + 32;
                if (((rmask >> (j / 9)) & 1) && ((cmask >> (j % 9)) & 1)) {
                    if (v1 > bv || (v1 == bv && j < bidx)) { bv = v1; bidx = j; }
                }
                j = t + 64;
                if (j < 81 && ((rmask >> (j / 9)) & 1) && ((cmask >> (j % 9)) & 1)) {
                    if (v2 > bv || (v2 == bv && j < bidx)) { bv = v2; bidx = j; }
                }
#pragma unroll
                for (int off = 16; off; off >>= 1) {
                    float ov = __shfl_xor_sync(0xffffffffu, bv, off);
                    int   oi = __shfl_xor_sync(0xffffffffu, bidx, off);
                    if (ov > bv || (ov == bv && oi < bidx)) { bv = ov; bidx = oi; }
                }
                totalv = fmaf(fmaxf(bv, 0.f), beta, totalv);
                beta *= 0.5f;
                rmask &= ~(1u << (bidx / 9));
                cmask &= ~(1u << (bidx % 9));
            }
            if (t == 0) out[((size_t)b * NQ_ + n) * WAY_ + m] = totalv;
        }
    }
}

// ---------------------------------------------------------------------------
extern "C" void kernel_launch(void* const* d_in, const int* in_sizes, int n_in,
                              void* d_out, int out_size) {
    const float* data   = (const float*)d_in[0];
    const float* conv_w = (const float*)d_in[1];
    (void)in_sizes; (void)n_in; (void)out_size;

    static bool attr_set = false;
    if (!attr_set) {
        cudaFuncSetAttribute(k_gemm, cudaFuncAttributeMaxDynamicSharedMemorySize, SMT);
        attr_set = true;
    }

    k_prepw<<<(CO * KD + 255) / 256, 256>>>(conv_w);
    k_prepx<<<NS, 128>>>(data);
    k_gemm<<<NTOT / TNB, 640, SMT>>>();
    k_sim<<<B_ * NQ_, 128>>>((float*)d_out);
}

// round 6
// speedup vs baseline: 1.1733x; 1.1733x over previous
#include <cuda_runtime.h>
#include <cuda_fp16.h>
#include <cstdint>
#include <math.h>

// ---------------- problem constants ----------------
#define NS   5760
#define CO   640
#define KD   192
#define NPOS 16
#define B_   8
#define WAY_ 5
#define NQ_  75
#define P_   9
#define NTOT (NS * NPOS)     // 92160
#define KE2  576             // 3 * 192 fp16-split K
#define TNB  64              // N per block = 4 images
#define KC   32              // K halves per chunk
#define NCH  18              // 576 / 32

// ---------------- device scratch ----------------
__device__ __align__(128) __half g_X[(size_t)NTOT * KE2];  // 106 MB
__device__ __align__(128) __half g_W[(size_t)CO * KE2];    // 737 KB
__device__ float g_u[(size_t)NS * CO];

__device__ __forceinline__ uint32_t smem_u32(const void* p) {
    uint32_t a;
    asm("{ .reg .u64 t; cvta.to.shared.u64 t, %1; cvt.u32.u64 %0, t; }"
        : "=r"(a) : "l"(p));
    return a;
}

// ---------------------------------------------------------------------------
// Prep W: fp16 split, K-concat [w0 | w0 | w1]
// ---------------------------------------------------------------------------
__global__ void k_prepw(const float* __restrict__ w) {
    int i = blockIdx.x * 256 + threadIdx.x;
    if (i >= CO * KD) return;
    int ch = i / KD, k = i % KD;
    float v = w[i];
    __half h0 = __float2half_rn(v);
    __half h1 = __float2half_rn(v - __half2float(h0));
    size_t b = (size_t)ch * KE2;
    g_W[b + k]       = h0;
    g_W[b + 192 + k] = h0;
    g_W[b + 384 + k] = h1;
}

// ---------------------------------------------------------------------------
// Prep X: im2col + fp16 split, K-concat [x0 | x1 | x0]. One block per image.
// ---------------------------------------------------------------------------
__global__ void __launch_bounds__(128) k_prepx(const float* __restrict__ data) {
    __shared__ __align__(16) __half xsm[NPOS * KE2];   // 18 KB
    const int s = blockIdx.x, t = threadIdx.x;
    const float* img = data + (size_t)s * 3072;
    for (int i = t; i < 3072; i += 128) {
        float v = img[i];
        int ci = i >> 10, row = (i >> 5) & 31, col = i & 31;
        int k   = ci * 64 + (row & 7) * 8 + (col & 7);
        int pos = (row >> 3) * 4 + (col >> 3);
        __half h0 = __float2half_rn(v);
        __half h1 = __float2half_rn(v - __half2float(h0));
        int r = pos * KE2;
        xsm[r + k]       = h0;
        xsm[r + 192 + k] = h1;
        xsm[r + 384 + k] = h0;
    }
    __syncthreads();
    uint4* dst = reinterpret_cast<uint4*>(g_X + (size_t)s * NPOS * KE2);
    const uint4* src = reinterpret_cast<const uint4*>(xsm);
    for (int g = t; g < NPOS * KE2 / 8; g += 128) dst[g] = src[g];
}

// ---------------------------------------------------------------------------
// Fused GEMM + norms. Triple-buffered A, ONE barrier per chunk.
// ---------------------------------------------------------------------------
#define BST     584                       // B row stride (halves): 1168 B
#define AST     40                        // A row stride (halves): 80 B
#define OFF_B   0
#define BSZ     (64 * BST * 2)            // 74752
#define OFF_A   BSZ
#define ABUF_SZ (640 * AST * 2)           // 51200
#define SMT     (OFF_A + 3 * ABUF_SZ)     // 228352
// epilogue scratch aliased over A buffers (valid after final compute + bar)
#define OFF_SSQ OFF_A
#define OFF_SS2 (OFF_A + 256)
#define OFF_VSM (OFF_A + 272)

#define LDSM4(r0, r1, r2, r3, ad) \
    asm volatile("ldmatrix.sync.aligned.m8n8.x4.shared.b16 {%0,%1,%2,%3},[%4];" \
                 : "=r"(r0), "=r"(r1), "=r"(r2), "=r"(r3) : "r"(ad))

__global__ void __launch_bounds__(640, 1) k_gemm() {
    extern __shared__ char sm[];
    const int t = threadIdx.x, w = t >> 5, lane = t & 31;
    const int bid = blockIdx.x;
    const uint32_t sb = smem_u32(sm);

    // --- A chunk via cp.async: 640 rows x 64 B, 4 x 16B per thread ---
    auto issueA = [&](int c, int buf) {
        const int kc = KC * c;
#pragma unroll
        for (int i = 0; i < 4; i++) {
            int g = t + 640 * i;
            int row = g >> 2, part = g & 3;
            const __half* src = g_W + (size_t)row * KE2 + kc + part * 8;
            uint32_t dst = sb + OFF_A + buf * ABUF_SZ + row * (AST * 2) + part * 16;
            asm volatile("cp.async.cg.shared.global [%0], [%1], 16;"
                         :: "r"(dst), "l"(src));
        }
        asm volatile("cp.async.commit_group;");
    };
    issueA(0, 0);
    issueA(1, 1);

    // --- stage B (64 rows x 576 halves) ---
    const __half* Xb = g_X + (size_t)bid * TNB * KE2;
    for (int g = t; g < 64 * 72; g += 640) {
        int row = g / 72, part = g % 72;
        uint4 v = *reinterpret_cast<const uint4*>(Xb + (size_t)row * KE2 + part * 8);
        *reinterpret_cast<uint4*>(sm + OFF_B + row * (BST * 2) + part * 16) = v;
    }

    float acc[2][8][4];
#pragma unroll
    for (int mt = 0; mt < 2; mt++)
#pragma unroll
        for (int nt = 0; nt < 8; nt++)
#pragma unroll
            for (int c = 0; c < 4; c++) acc[mt][nt][c] = 0.f;

    // ldmatrix per-lane base addresses
    const int lm = lane >> 3;
    const uint32_t aAddr = sb + OFF_A +
        ((w * 32 + (lm & 1) * 8 + (lane & 7)) * AST + (lm >> 1) * 8) * 2;
    const uint32_t bAddr = sb + OFF_B +
        (((lm >> 1) * 8 + (lane & 7)) * BST + (lm & 1) * 8) * 2;

    for (int c = 0; c < NCH; c++) {
        // wait for chunk c's group (allow the c+1 prefetch to stay in flight)
        if (c + 1 < NCH) asm volatile("cp.async.wait_group 1;");
        else             asm volatile("cp.async.wait_group 0;");
        __syncthreads();   // data visible to all; all warps done computing c-1
        if (c + 2 < NCH) issueA(c + 2, (c + 2) % 3);   // buffer of c-1 is free

        const uint32_t aBuf = aAddr + (c % 3) * ABUF_SZ;
#pragma unroll
        for (int ks = 0; ks < 2; ks++) {
            uint32_t a0[4], a1[4];
            uint32_t aBase = aBuf + ks * 32;
            LDSM4(a0[0], a0[1], a0[2], a0[3], aBase);
            LDSM4(a1[0], a1[1], a1[2], a1[3], aBase + 16 * AST * 2);
#pragma unroll
            for (int ntp = 0; ntp < 4; ntp++) {
                uint32_t b[4];
                LDSM4(b[0], b[1], b[2], b[3],
                      bAddr + ntp * (16 * BST * 2) + c * (KC * 2) + ks * 32);
#pragma unroll
                for (int sub = 0; sub < 2; sub++) {
                    int nt = 2 * ntp + sub;
                    asm volatile(
                        "mma.sync.aligned.m16n8k16.row.col.f32.f16.f16.f32 "
                        "{%0,%1,%2,%3},{%4,%5,%6,%7},{%8,%9},{%0,%1,%2,%3};"
                        : "+f"(acc[0][nt][0]), "+f"(acc[0][nt][1]),
                          "+f"(acc[0][nt][2]), "+f"(acc[0][nt][3])
                        : "r"(a0[0]), "r"(a0[1]), "r"(a0[2]), "r"(a0[3]),
                          "r"(b[2 * sub]), "r"(b[2 * sub + 1]));
                    asm volatile(
                        "mma.sync.aligned.m16n8k16.row.col.f32.f16.f16.f32 "
                        "{%0,%1,%2,%3},{%4,%5,%6,%7},{%8,%9},{%0,%1,%2,%3};"
                        : "+f"(acc[1][nt][0]), "+f"(acc[1][nt][1]),
                          "+f"(acc[1][nt][2]), "+f"(acc[1][nt][3])
                        : "r"(a1[0]), "r"(a1[1]), "r"(a1[2]), "r"(a1[3]),
                          "r"(b[2 * sub]), "r"(b[2 * sub + 1]));
                }
            }
        }
    }
    __syncthreads();   // all compute done; A buffers now reusable as scratch

    float* ssq = reinterpret_cast<float*>(sm + OFF_SSQ);
    float* ss2 = reinterpret_cast<float*>(sm + OFF_SS2);
    float* vsm = reinterpret_cast<float*>(sm + OFF_VSM);
    if (t < 64) ssq[t] = 0.f;
    if (t >= 64 && t < 68) ss2[t - 64] = 0.f;
    __syncthreads();

    // ---- epilogue: per-position channel L2-norm ----
    {
        float cs[16];
#pragma unroll
        for (int nt = 0; nt < 8; nt++)
#pragma unroll
            for (int par = 0; par < 2; par++) {
                float s = 0.f;
#pragma unroll
                for (int mt = 0; mt < 2; mt++) {
                    float x0 = acc[mt][nt][par], x1 = acc[mt][nt][2 + par];
                    s = fmaf(x0, x0, s);
                    s = fmaf(x1, x1, s);
                }
                cs[nt * 2 + par] = s;
            }
#pragma unroll
        for (int i = 0; i < 16; i++) {
            cs[i] += __shfl_xor_sync(0xffffffffu, cs[i], 4);
            cs[i] += __shfl_xor_sync(0xffffffffu, cs[i], 8);
            cs[i] += __shfl_xor_sync(0xffffffffu, cs[i], 16);
        }
        if (lane < 4) {
#pragma unroll
            for (int nt = 0; nt < 8; nt++)
#pragma unroll
                for (int par = 0; par < 2; par++)
                    atomicAdd(&ssq[nt * 8 + lane * 2 + par], cs[nt * 2 + par]);
        }
    }
    __syncthreads();
    if (t < 64) ssq[t] = 1.f / fmaxf(sqrtf(ssq[t]), 1e-12f);
    __syncthreads();

    // ---- pool over positions + final channel L2-norm ----
    float sq[4] = {0.f, 0.f, 0.f, 0.f};
#pragma unroll
    for (int mt = 0; mt < 2; mt++)
#pragma unroll
        for (int h = 0; h < 2; h++)
#pragma unroll
            for (int j = 0; j < 4; j++) {
                float s = 0.f;
#pragma unroll
                for (int ntl = 0; ntl < 2; ntl++) {
                    int nt = 2 * j + ntl;
#pragma unroll
                    for (int par = 0; par < 2; par++) {
                        int col = nt * 8 + (lane & 3) * 2 + par;
                        s = fmaf(acc[mt][nt][h * 2 + par], ssq[col], s);
                    }
                }
                s += __shfl_xor_sync(0xffffffffu, s, 1);
                s += __shfl_xor_sync(0xffffffffu, s, 2);
                if ((lane & 3) == 0) {
                    int row = w * 32 + mt * 16 + h * 8 + (lane >> 2);
                    float v = s * 0.0625f;
                    vsm[row * 4 + j] = v;
                    sq[j] = fmaf(v, v, sq[j]);
                }
            }
#pragma unroll
    for (int j = 0; j < 4; j++) {
        sq[j] += __shfl_xor_sync(0xffffffffu, sq[j], 4);
        sq[j] += __shfl_xor_sync(0xffffffffu, sq[j], 8);
        sq[j] += __shfl_xor_sync(0xffffffffu, sq[j], 16);
    }
    if (lane == 0)
#pragma unroll
        for (int j = 0; j < 4; j++) atomicAdd(&ss2[j], sq[j]);
    __syncthreads();
    if (t < 4) ss2[t] = 1.f / fmaxf(sqrtf(ss2[t]), 1e-12f);
    __syncthreads();

    for (int g = t; g < 2560; g += 640) {
        int ch = g >> 2, j = g & 3;
        g_u[(size_t)(4 * bid + j) * CO + ch] = vsm[ch * 4 + j] * ss2[j];
    }
}

// ---------------------------------------------------------------------------
// Sim + greedy pruning (unchanged passing version).
// ---------------------------------------------------------------------------
#define QSTRIDE 644

__global__ void __launch_bounds__(128) k_sim(float* __restrict__ out) {
    __shared__ float qsm[9 * QSTRIDE];
    __shared__ float ssm[9 * QSTRIDE];
    __shared__ float simm[81];

    const int b = blockIdx.x / NQ_;
    const int n = blockIdx.x % NQ_;
    const int t = threadIdx.x;

    const float* qb = g_u + ((size_t)(b * 80 + WAY_ + n) * P_) * CO;
    for (int i = t; i < 9 * 160; i += 128) {
        int r = i / 160, c4 = (i % 160) * 4;
        *reinterpret_cast<float4*>(&qsm[r * QSTRIDE + c4]) =
            *reinterpret_cast<const float4*>(qb + (size_t)r * CO + c4);
    }

    for (int m = 0; m < WAY_; m++) {
        const float* sb2 = g_u + ((size_t)(b * 80 + m) * P_) * CO;
        __syncthreads();
        for (int i = t; i < 9 * 160; i += 128) {
            int r = i / 160, c4 = (i % 160) * 4;
            *reinterpret_cast<float4*>(&ssm[r * QSTRIDE + c4]) =
                *reinterpret_cast<const float4*>(sb2 + (size_t)r * CO + c4);
        }
        __syncthreads();

        if (t < 81) {
            const int h = t / 9, wq = t % 9;
            const float* sr = &ssm[h * QSTRIDE];
            const float* qr = &qsm[wq * QSTRIDE];
            float d = 0.f;
            for (int c = 0; c < CO; c += 4) {
                float4 a = *reinterpret_cast<const float4*>(sr + c);
                float4 q = *reinterpret_cast<const float4*>(qr + c);
                d = fmaf(a.x, q.x, d);
                d = fmaf(a.y, q.y, d);
                d = fmaf(a.z, q.z, d);
                d = fmaf(a.w, q.w, d);
            }
            simm[t] = d;
        }
        __syncthreads();

        if (t < 32) {
            float v0 = simm[t];
            float v1 = simm[t + 32];
            float v2 = (t + 64 < 81) ? simm[t + 64] : -1e30f;
            unsigned rmask = 0x1FFu, cmask = 0x1FFu;
            float totalv = 0.f, beta = 1.f;
            for (int it = 0; it < 9; it++) {
                float bv = -1e30f;
                int bidx = 999;
                int j = t;
                if (((rmask >> (j / 9)) & 1) && ((cmask >> (j % 9)) & 1)) {
                    bv = v0; bidx = j;
                }
                j = t + 32;
                if (((rmask >> (j / 9)) & 1) && ((cmask >> (j % 9)) & 1)) {
                    if (v1 > bv || (v1 == bv && j < bidx)) { bv = v1; bidx = j; }
                }
                j = t + 64;
                if (j < 81 && ((rmask >> (j / 9)) & 1) && ((cmask >> (j % 9)) & 1)) {
                    if (v2 > bv || (v2 == bv && j < bidx)) { bv = v2; bidx = j; }
                }
#pragma unroll
                for (int off = 16; off; off >>= 1) {
                    float ov = __shfl_xor_sync(0xffffffffu, bv, off);
                    int   oi = __shfl_xor_sync(0xffffffffu, bidx, off);
                    if (ov > bv || (ov == bv && oi < bidx)) { bv = ov; bidx = oi; }
                }
                totalv = fmaf(fmaxf(bv, 0.f), beta, totalv);
                beta *= 0.5f;
                rmask &= ~(1u << (bidx / 9));
                cmask &= ~(1u << (bidx % 9));
            }
            if (t == 0) out[((size_t)b * NQ_ + n) * WAY_ + m] = totalv;
        }
    }
}

// ---------------------------------------------------------------------------
extern "C" void kernel_launch(void* const* d_in, const int* in_sizes, int n_in,
                              void* d_out, int out_size) {
    const float* data   = (const float*)d_in[0];
    const float* conv_w = (const float*)d_in[1];
    (void)in_sizes; (void)n_in; (void)out_size;

    static bool attr_set = false;
    if (!attr_set) {
        cudaFuncSetAttribute(k_gemm, cudaFuncAttributeMaxDynamicSharedMemorySize, SMT);
        attr_set = true;
    }

    k_prepw<<<(CO * KD + 255) / 256, 256>>>(conv_w);
    k_prepx<<<NS, 128>>>(data);
    k_gemm<<<NTOT / TNB, 640, SMT>>>();
    k_sim<<<B_ * NQ_, 128>>>((float*)d_out);
}